// round 11
// baseline (speedup 1.0000x reference)
#include <cuda_runtime.h>
#include <cuda_fp16.h>
#include <cstdint>

#define PP 2048
#define VV 32000
#define DD 100
#define NT1 256
#define NSEG 10
#define SEGV (VV / NSEG)          // 3200

#define MT 64
#define GKT 64
#define GNSPLIT 50
#define GKSEG (VV / GNSPLIT)      // 640
#define GTHR 128
#define NSTG 3

// ---- static device scratch (no dynamic allocation allowed) ----
__device__ __align__(16) __half g_wscr[(size_t)PP * VV];   // exp(z - mz_seg), fp16
__device__ __align__(16) __half g_WhT[(size_t)DD * VV];    // W transposed, fp16
__device__ __align__(16) float  g_part[GNSPLIT][PP][104];  // GEMM k-split partials
__device__ float4 g_stA[PP * NSEG];    // (m1, e1, a1, -)
__device__ float4 g_stB[PP * NSEG];    // (mz, e2, ai_bits, -)
__device__ float g_scale[PP * NSEG];   // exp(mz_seg - MZ)/Z2, or 0 if row inactive
__device__ float g_ent[PP];
__device__ int   g_rows[PP];           // compacted masked-row indices
__device__ int   g_slot[PP];           // row -> compacted slot (masked rows only)
__device__ int   g_safe[PP];
__device__ int   g_cnt[PP];            // per-row finished-segment counter (self-resetting)
__device__ int   g_nmask;

// -log(u + 1e-20), accurate near u==1 (where __logf's absolute error would
// corrupt the gumbel tail / argmax). Series uses exact d = 1-u for u >= 0.75.
__device__ __forceinline__ float neglog_u(float u) {
    float ue = u + 1e-20f;
    float d = 1.0f - ue;
    float s = d * (1.0f + d * (0.5f + d * (0.33333333f + d * (0.25f + d * (0.2f
             + d * (0.16666667f + d * (0.14285714f + d * (0.125f
             + d * 0.11111111f))))))));
    float l = -__logf(ue);
    return (ue >= 0.75f) ? s : l;
}
__device__ __forceinline__ float gumbel_g(float u) {
    return -__logf(neglog_u(u) + 1e-20f);
}

// ======== kernel 0: W transpose->f16  +  masked-row scan (block 0) ========
#define TK 64
__global__ void k_wconv(const float* __restrict__ W, const int* __restrict__ mask) {
    __shared__ float s[TK][DD + 1];
    const int k0 = blockIdx.x * TK;
    const int tid = threadIdx.x;
    for (int idx = tid; idx < TK * DD; idx += 256) {
        int r = idx / DD, d = idx - r * DD;
        s[r][d] = W[(size_t)(k0 + r) * DD + d];
    }
    __syncthreads();
    for (int idx = tid; idx < TK * DD; idx += 256) {
        int d = idx >> 6, r = idx & 63;
        g_WhT[(size_t)d * VV + k0 + r] = __float2half(s[r][d]);
    }
    if (blockIdx.x == 0) {
        __shared__ int sp[256];
        int m[8], loc = 0;
        #pragma unroll
        for (int j = 0; j < 8; j++) { m[j] = mask[tid * 8 + j]; loc += m[j]; }
        sp[tid] = loc;
        __syncthreads();
        for (int off = 1; off < 256; off <<= 1) {
            int v = (tid >= off) ? sp[tid - off] : 0;
            __syncthreads();
            sp[tid] += v;
            __syncthreads();
        }
        int excl = sp[tid] - loc;
        #pragma unroll
        for (int j = 0; j < 8; j++)
            if (m[j]) { g_rows[excl] = tid * 8 + j; g_slot[tid * 8 + j] = excl; excl++; }
        if (tid == 255) g_nmask = sp[255];
    }
}

// ======== kernel 1: stats (dense over compacted rows) + fused combine ========
__global__ void k_stats(const float* __restrict__ logits,
                        const float* __restrict__ gumb,
                        const int* __restrict__ inp_word,
                        float* __restrict__ out)
{
    const int bx = blockIdx.x;
    if (bx >= g_nmask) return;
    const int pos = g_rows[bx];
    const int seg = blockIdx.y;
    const int tid = threadIdx.x;
    const int base = seg * SEGV;
    const float4* x4 = (const float4*)(logits + (size_t)pos * VV + base);
    const float4* u4 = (const float4*)(gumb   + (size_t)pos * VV + base);

    const int iA = 2 * tid;
    const int iB = 512 + 2 * tid;
    const bool vB = (tid < 144);

    float4 XV[4], UV[4];
    XV[0] = __ldcs(x4 + iA);     XV[1] = __ldcs(x4 + iA + 1);
    UV[0] = __ldcs(u4 + iA);     UV[1] = __ldcs(u4 + iA + 1);
    if (vB) {
        XV[2] = __ldcs(x4 + iB); XV[3] = __ldcs(x4 + iB + 1);
        UV[2] = __ldcs(u4 + iB); UV[3] = __ldcs(u4 + iB + 1);
    } else {
        XV[2] = make_float4(-3.0e38f, -3.0e38f, -3.0e38f, -3.0e38f);
        XV[3] = XV[2];
        UV[2] = make_float4(0.5f, 0.5f, 0.5f, 0.5f);
        UV[3] = UV[2];
    }

    float x[16], z[16];
    float m1 = -3.0e38f, mz = -3.0e38f;
    int ai = 0;
    #pragma unroll
    for (int j = 0; j < 4; j++) {
        const int e0 = base + ((j < 2) ? (iA + j) : (iB + j - 2)) * 4;
        const float* xe = &XV[j].x;
        const float* ue = &UV[j].x;
        #pragma unroll
        for (int e = 0; e < 4; e++) {
            float xv = xe[e];
            float zv = xv + gumbel_g(ue[e]);
            x[j*4+e] = xv; z[j*4+e] = zv;
            m1 = fmaxf(m1, xv);
            if (zv > mz) { mz = zv; ai = e0 + e; }
        }
    }
    const unsigned FULL = 0xffffffffu;
    #pragma unroll
    for (int off = 16; off; off >>= 1) {
        m1 = fmaxf(m1, __shfl_down_sync(FULL, m1, off));
        float oz = __shfl_down_sync(FULL, mz, off);
        int   oi = __shfl_down_sync(FULL, ai, off);
        if (oz > mz || (oz == mz && oi < ai)) { mz = oz; ai = oi; }
    }
    __shared__ float sA[8], sB[8];
    __shared__ int   sI[8];
    const int wid = tid >> 5, lane = tid & 31;
    if (lane == 0) { sA[wid] = m1; sB[wid] = mz; sI[wid] = ai; }
    __syncthreads();
    if (tid == 0) {
        #pragma unroll
        for (int w = 1; w < 8; w++) {
            m1 = fmaxf(m1, sA[w]);
            if (sB[w] > mz || (sB[w] == mz && sI[w] < ai)) { mz = sB[w]; ai = sI[w]; }
        }
        sA[0] = m1; sB[0] = mz; sI[0] = ai;
    }
    __syncthreads();
    const float M1 = sA[0], MZ = sB[0];
    const int   AI = sI[0];

    float e1 = 0.f, a1 = 0.f, e2 = 0.f;
    __half* wr = g_wscr + (size_t)pos * VV + base;
    {   // chunk A (all threads)
        float w[8];
        #pragma unroll
        for (int q = 0; q < 8; q++) {
            float t = x[q] - M1;
            float p = __expf(t);
            e1 += p; a1 += p * t;
            w[q] = __expf(z[q] - MZ);
            e2 += w[q];
        }
        __half2 h0 = __floats2half2_rn(w[0], w[1]);
        __half2 h1 = __floats2half2_rn(w[2], w[3]);
        __half2 h2 = __floats2half2_rn(w[4], w[5]);
        __half2 h3 = __floats2half2_rn(w[6], w[7]);
        uint4 pk;
        pk.x = *(uint32_t*)&h0; pk.y = *(uint32_t*)&h1;
        pk.z = *(uint32_t*)&h2; pk.w = *(uint32_t*)&h3;
        *(uint4*)(wr + iA * 4) = pk;
    }
    {   // chunk B
        float w[8];
        #pragma unroll
        for (int q = 8; q < 16; q++) {
            float t = x[q] - M1;
            float p = __expf(t);
            e1 += p; a1 += p * t;
            w[q-8] = __expf(z[q] - MZ);
            e2 += w[q-8];
        }
        if (vB) {
            __half2 h0 = __floats2half2_rn(w[0], w[1]);
            __half2 h1 = __floats2half2_rn(w[2], w[3]);
            __half2 h2 = __floats2half2_rn(w[4], w[5]);
            __half2 h3 = __floats2half2_rn(w[6], w[7]);
            uint4 pk;
            pk.x = *(uint32_t*)&h0; pk.y = *(uint32_t*)&h1;
            pk.z = *(uint32_t*)&h2; pk.w = *(uint32_t*)&h3;
            *(uint4*)(wr + iB * 4) = pk;
        }
    }
    #pragma unroll
    for (int off = 16; off; off >>= 1) {
        e1 += __shfl_down_sync(FULL, e1, off);
        a1 += __shfl_down_sync(FULL, a1, off);
        e2 += __shfl_down_sync(FULL, e2, off);
    }
    __shared__ float sE1[8], sA1[8], sE2[8];
    if (lane == 0) { sE1[wid] = e1; sA1[wid] = a1; sE2[wid] = e2; }
    __syncthreads();
    __shared__ int sWin;
    if (tid == 0) {
        float E1 = 0.f, A1 = 0.f, E2 = 0.f;
        #pragma unroll
        for (int w2 = 0; w2 < 8; w2++) { E1 += sE1[w2]; A1 += sA1[w2]; E2 += sE2[w2]; }
        const int idx = pos * NSEG + seg;
        g_stA[idx] = make_float4(M1, E1, A1, 0.f);
        g_stB[idx] = make_float4(MZ, E2, __int_as_float(AI), 0.f);
        __threadfence();                       // publish stats before counting
        int old = atomicAdd(&g_cnt[pos], 1);
        sWin = (old == NSEG - 1);
    }
    __syncthreads();
    // ---- fused per-row combine: warp 0 of the last-finishing CTA ----
    if (sWin && tid < 32) {
        __threadfence();                       // acquire all segments' stats
        const bool v = tid < NSEG;
        const int idx = pos * NSEG + tid;
        float4 pa = v ? g_stA[idx] : make_float4(-3.0e38f, 0.f, 0.f, 0.f);
        float4 pb = v ? g_stB[idx] : make_float4(-3.0e38f, 0.f, __int_as_float(0x7fffffff), 0.f);
        float cm1 = pa.x, ce1 = pa.y, ca1 = pa.z;
        float cmz = pb.x, ce2 = pb.y;
        int   cai = __float_as_int(pb.z);
        float CM1 = cm1, CMZ = cmz; int CAI = cai;
        #pragma unroll
        for (int off = 16; off; off >>= 1) {
            CM1 = fmaxf(CM1, __shfl_xor_sync(FULL, CM1, off));
            float omz = __shfl_xor_sync(FULL, CMZ, off);
            int   oai = __shfl_xor_sync(FULL, CAI, off);
            if (omz > CMZ || (omz == CMZ && oai < CAI)) { CMZ = omz; CAI = oai; }
        }
        float E1 = v ? ce1 * expf(cm1 - CM1) : 0.f;
        float A1 = v ? (ca1 + (cm1 - CM1) * ce1) * expf(cm1 - CM1) : 0.f;
        float E2 = v ? ce2 * expf(cmz - CMZ) : 0.f;
        #pragma unroll
        for (int off = 16; off; off >>= 1) {
            E1 += __shfl_xor_sync(FULL, E1, off);
            A1 += __shfl_xor_sync(FULL, A1, off);
            E2 += __shfl_xor_sync(FULL, E2, off);
        }
        const int iw = inp_word[pos];
        const int safe = (CAI != iw) ? 1 : 0;
        if (v) g_scale[idx] = safe ? (expf(cmz - CMZ) / E2) : 0.0f;
        if (tid == 0) {
            g_ent[pos]  = A1 / E1 - logf(E1);
            out[pos]    = safe ? (float)CAI : 0.0f;   // UNK_ID = 0
            g_safe[pos] = safe;
            g_cnt[pos]  = 0;                          // reset for next graph replay
        }
    }
}

// ======== kernel 2: fp16 GEMM, 3-stage cp.async, partial epilogue ========
__device__ __forceinline__ uint32_t s2u(const void* p) {
    return (uint32_t)__cvta_generic_to_shared(p);
}
__device__ __forceinline__ void ldsm4(uint32_t* r, uint32_t a) {
    asm volatile("ldmatrix.sync.aligned.m8n8.x4.shared.b16 {%0,%1,%2,%3},[%4];"
        : "=r"(r[0]), "=r"(r[1]), "=r"(r[2]), "=r"(r[3]) : "r"(a));
}
__device__ __forceinline__ void mma16816(float* c, const uint32_t* a,
                                         uint32_t b0, uint32_t b1) {
    asm volatile("mma.sync.aligned.m16n8k16.row.col.f32.f16.f16.f32 "
        "{%0,%1,%2,%3},{%4,%5,%6,%7},{%8,%9},{%0,%1,%2,%3};"
        : "+f"(c[0]), "+f"(c[1]), "+f"(c[2]), "+f"(c[3])
        : "r"(a[0]), "r"(a[1]), "r"(a[2]), "r"(a[3]), "r"(b0), "r"(b1));
}
__device__ __forceinline__ void cpa16(uint32_t s, const void* g) {
    asm volatile("cp.async.cg.shared.global [%0], [%1], 16;" :: "r"(s), "l"(g));
}
#define CP_COMMIT() asm volatile("cp.async.commit_group;")
#define CP_WAIT2()  asm volatile("cp.async.wait_group 2;")

#define ASTR 72
#define BSTR 72
#define NITER (GKSEG / GKT)    // 10

__global__ void __launch_bounds__(GTHR, 3) k_gemm(void)
{
    const int nm = g_nmask;
    const int rowBase = blockIdx.x * MT;
    if (rowBase >= nm) return;

    __shared__ __align__(16) __half As[NSTG][MT * ASTR];
    __shared__ __align__(16) __half Bs[NSTG][104 * BSTR];
    __shared__ int sRow[MT];

    const int kBase = blockIdx.y * GKSEG;
    const int tid = threadIdx.x;
    const int wid = tid >> 5, lane = tid & 31;
    const int grp = lane >> 2, tig = lane & 3;

    if (tid < MT) {
        int slot = rowBase + tid;
        sRow[tid] = g_rows[(slot < nm) ? slot : 0];
    }
    for (int i = tid; i < NSTG * 144; i += GTHR) {
        int st = i / 144, rem = i % 144;
        int r = rem / 36, c2 = rem % 36;
        ((uint32_t*)(Bs[st] + (100 + r) * BSTR))[c2] = 0u;
    }
    __syncthreads();

    float c[13][4];
    #pragma unroll
    for (int j = 0; j < 13; j++) { c[j][0]=0.f; c[j][1]=0.f; c[j][2]=0.f; c[j][3]=0.f; }

    const __half* bG = g_WhT + kBase;

    auto load_stage = [&](int st, int kc) {
        #pragma unroll
        for (int it = 0; it < 7; it++) {
            int idx = tid + it * GTHR;
            if (idx < 800) {
                int n = idx >> 3, g = idx & 7;
                cpa16(s2u(Bs[st] + n * BSTR + g * 8),
                      bG + (size_t)n * VV + kc + g * 8);
            }
        }
        #pragma unroll
        for (int it = 0; it < 4; it++) {
            int idx = tid + it * GTHR;
            int r = idx >> 3, g = idx & 7;
            cpa16(s2u(As[st] + r * ASTR + g * 8),
                  g_wscr + (size_t)sRow[r] * VV + kBase + kc + g * 8);
        }
        CP_COMMIT();
    };

    load_stage(0, 0);
    load_stage(1, GKT);
    #pragma unroll 1
    for (int i = 0; i < NITER; i++) {
        if (i + 2 < NITER) load_stage((i + 2) % NSTG, (i + 2) * GKT);
        else CP_COMMIT();
        CP_WAIT2();
        __syncthreads();

        const int s = i % NSTG;
        const int wrow = wid * 16;
        #pragma unroll
        for (int kh = 0; kh < 2; kh++) {
            const int ar = wrow + (lane & 7) + (lane & 8);
            const int ac = kh * 32 + ((lane >> 4) << 3);
            uint32_t a0[4], a1[4];
            ldsm4(a0, s2u(As[s] + ar * ASTR + ac));
            ldsm4(a1, s2u(As[s] + ar * ASTR + ac + 16));
            const int bc = kh * 32 + ((lane >> 3) << 3);
            #pragma unroll
            for (int j = 0; j < 13; j++) {
                uint32_t b[4];
                ldsm4(b, s2u(Bs[s] + (j * 8 + (lane & 7)) * BSTR + bc));
                mma16816(c[j], a0, b[0], b[1]);
                mma16816(c[j], a1, b[2], b[3]);
            }
        }
        __syncthreads();
    }

    const int sseg = blockIdx.y / 5;   // 640*5 = 3200 = stats segment
    const int sl0 = wid * 16 + grp;
    const int sl1 = sl0 + 8;
    const int r0 = sRow[sl0], r1 = sRow[sl1];
    const float s0 = g_scale[r0 * NSEG + sseg];
    const float s1 = g_scale[r1 * NSEG + sseg];
    float* p0 = &g_part[blockIdx.y][rowBase + sl0][0];
    float* p1 = &g_part[blockIdx.y][rowBase + sl1][0];
    #pragma unroll
    for (int j = 0; j < 13; j++) {
        int col = j * 8 + tig * 2;
        __stcg((float2*)(p0 + col), make_float2(c[j][0] * s0, c[j][1] * s0));
        __stcg((float2*)(p1 + col), make_float2(c[j][2] * s1, c[j][3] * s1));
    }
}

// ======== kernel 3: materialize outputs (emb rows + ent loss) ========
__global__ void k_red(const int* __restrict__ inp_word,
                      const int* __restrict__ obf_mask,
                      const float* __restrict__ W,
                      float* __restrict__ out)
{
    const int row = blockIdx.x;
    const int tid = threadIdx.x;
    float* out_emb = out + PP;
    const int mk = obf_mask[row];
    if (!mk) {
        const int iw = inp_word[row];
        if (tid == 0) out[row] = (float)iw;
        for (int d = tid; d < DD; d += 128)
            out_emb[(size_t)row * DD + d] = W[(size_t)iw * DD + d];
    } else if (!g_safe[row]) {
        for (int d = tid; d < DD; d += 128)
            out_emb[(size_t)row * DD + d] = W[d];   // UNK embedding
    } else {
        const int b = g_slot[row];
        if (tid < DD) {
            float acc = 0.f;
            #pragma unroll 10
            for (int s = 0; s < GNSPLIT; s++)
                acc += __ldcg(&g_part[s][b][tid]);
            out_emb[(size_t)row * DD + tid] = acc;
        }
    }
    // entropy-loss reduction (block 0 only)
    if (blockIdx.x == 0) {
        __shared__ float ss[128];
        __shared__ int   sc[128];
        float s = 0.f; int c = 0;
        for (int i = tid; i < PP; i += 128) {
            int m = obf_mask[i];
            if (m) { s += g_ent[i]; c++; }
        }
        ss[tid] = s; sc[tid] = c;
        __syncthreads();
        for (int o = 64; o; o >>= 1) {
            if (tid < o) { ss[tid] += ss[tid + o]; sc[tid] += sc[tid + o]; }
            __syncthreads();
        }
        if (tid == 0)
            out[PP + (size_t)PP * DD] = ss[0] / ((float)sc[0] * (float)VV);
    }
}

// ======== launch ========
extern "C" void kernel_launch(void* const* d_in, const int* in_sizes, int n_in,
                              void* d_out, int out_size)
{
    (void)in_sizes; (void)n_in; (void)out_size;
    const float* logits = (const float*)d_in[0];
    const float* gumb   = (const float*)d_in[1];
    const int*   inp    = (const int*)d_in[2];
    const int*   mask   = (const int*)d_in[3];
    const float* W      = (const float*)d_in[4];
    float* out = (float*)d_out;

    k_wconv<<<VV / TK, 256>>>(W, mask);
    dim3 gs(PP, NSEG);
    k_stats<<<gs, NT1>>>(logits, gumb, inp, out);
    dim3 gg(PP / MT, GNSPLIT);
    k_gemm<<<gg, GTHR>>>();
    k_red<<<PP, 128>>>(inp, mask, W, out);
}

// round 12
// speedup vs baseline: 1.1039x; 1.1039x over previous
#include <cuda_runtime.h>
#include <cuda_fp16.h>
#include <cstdint>

#define PP 2048
#define VV 32000
#define DD 100
#define NT1 256
#define NSEG 10
#define SEGV (VV / NSEG)          // 3200

#define MT 64
#define GKT 64
#define GNSPLIT 50
#define GKSEG (VV / GNSPLIT)      // 640
#define GTHR 128
#define NSTG 3

// ---- static device scratch (no dynamic allocation allowed) ----
__device__ __align__(16) __half g_wscr[(size_t)PP * VV];   // exp(z - mz_seg), fp16
__device__ __align__(16) __half g_WhT[(size_t)DD * VV];    // W transposed, fp16
__device__ __align__(16) float  g_part[GNSPLIT][PP][104];  // GEMM k-split partials
__device__ float4 g_stA[PP * NSEG];    // (m1, e1, a1, -)
__device__ float4 g_stB[PP * NSEG];    // (mz, e2, ai_bits, -)
__device__ float g_scale[PP * NSEG];   // exp(mz_seg - MZ)/Z2, or 0 if row inactive
__device__ float g_ent[PP];
__device__ int   g_rows[PP];           // compacted masked-row indices
__device__ int   g_safe[PP];
__device__ int   g_nmask;

// -log(u + 1e-20), accurate near u==1 (where __logf's absolute error would
// corrupt the gumbel tail / argmax). Series uses exact d = 1-u for u >= 0.75.
__device__ __forceinline__ float neglog_u(float u) {
    float ue = u + 1e-20f;
    float d = 1.0f - ue;
    float s = d * (1.0f + d * (0.5f + d * (0.33333333f + d * (0.25f + d * (0.2f
             + d * (0.16666667f + d * (0.14285714f + d * (0.125f
             + d * 0.11111111f))))))));
    float l = -__logf(ue);
    return (ue >= 0.75f) ? s : l;
}
__device__ __forceinline__ float gumbel_g(float u) {
    return -__logf(neglog_u(u) + 1e-20f);
}

// ======== kernel 0: W transpose->f16  +  masked-row scan (block 0) ========
#define TK 64
__global__ void k_wconv(const float* __restrict__ W, const int* __restrict__ mask) {
    __shared__ float s[TK][DD + 1];
    const int k0 = blockIdx.x * TK;
    const int tid = threadIdx.x;
    for (int idx = tid; idx < TK * DD; idx += 256) {
        int r = idx / DD, d = idx - r * DD;
        s[r][d] = W[(size_t)(k0 + r) * DD + d];
    }
    __syncthreads();
    for (int idx = tid; idx < TK * DD; idx += 256) {
        int d = idx >> 6, r = idx & 63;
        g_WhT[(size_t)d * VV + k0 + r] = __float2half(s[r][d]);
    }
    if (blockIdx.x == 0) {
        __shared__ int sp[256];
        int m[8], loc = 0;
        #pragma unroll
        for (int j = 0; j < 8; j++) { m[j] = mask[tid * 8 + j]; loc += m[j]; }
        sp[tid] = loc;
        __syncthreads();
        for (int off = 1; off < 256; off <<= 1) {
            int v = (tid >= off) ? sp[tid - off] : 0;
            __syncthreads();
            sp[tid] += v;
            __syncthreads();
        }
        int excl = sp[tid] - loc;
        #pragma unroll
        for (int j = 0; j < 8; j++)
            if (m[j]) g_rows[excl++] = tid * 8 + j;
        if (tid == 255) g_nmask = sp[255];
    }
}

// ======== kernel 1: per-(row,segment) stats, single memory pass ========
__global__ void k_stats(const float* __restrict__ logits,
                        const float* __restrict__ gumb,
                        const int* __restrict__ obf_mask)
{
    const int pos = blockIdx.x;
    if (!obf_mask[pos]) return;
    const int seg = blockIdx.y;
    const int tid = threadIdx.x;
    const int base = seg * SEGV;
    const float4* x4 = (const float4*)(logits + (size_t)pos * VV + base);
    const float4* u4 = (const float4*)(gumb   + (size_t)pos * VV + base);

    const int iA = 2 * tid;
    const int iB = 512 + 2 * tid;
    const bool vB = (tid < 144);

    float4 XV[4], UV[4];
    XV[0] = __ldcs(x4 + iA);     XV[1] = __ldcs(x4 + iA + 1);
    UV[0] = __ldcs(u4 + iA);     UV[1] = __ldcs(u4 + iA + 1);
    if (vB) {
        XV[2] = __ldcs(x4 + iB); XV[3] = __ldcs(x4 + iB + 1);
        UV[2] = __ldcs(u4 + iB); UV[3] = __ldcs(u4 + iB + 1);
    } else {
        XV[2] = make_float4(-3.0e38f, -3.0e38f, -3.0e38f, -3.0e38f);
        XV[3] = XV[2];
        UV[2] = make_float4(0.5f, 0.5f, 0.5f, 0.5f);
        UV[3] = UV[2];
    }

    float x[16], z[16];
    float m1 = -3.0e38f, mz = -3.0e38f;
    int ai = 0;
    #pragma unroll
    for (int j = 0; j < 4; j++) {
        const int e0 = base + ((j < 2) ? (iA + j) : (iB + j - 2)) * 4;
        const float* xe = &XV[j].x;
        const float* ue = &UV[j].x;
        #pragma unroll
        for (int e = 0; e < 4; e++) {
            float xv = xe[e];
            float zv = xv + gumbel_g(ue[e]);
            x[j*4+e] = xv; z[j*4+e] = zv;
            m1 = fmaxf(m1, xv);
            if (zv > mz) { mz = zv; ai = e0 + e; }
        }
    }
    const unsigned FULL = 0xffffffffu;
    #pragma unroll
    for (int off = 16; off; off >>= 1) {
        m1 = fmaxf(m1, __shfl_down_sync(FULL, m1, off));
        float oz = __shfl_down_sync(FULL, mz, off);
        int   oi = __shfl_down_sync(FULL, ai, off);
        if (oz > mz || (oz == mz && oi < ai)) { mz = oz; ai = oi; }
    }
    __shared__ float sA[8], sB[8];
    __shared__ int   sI[8];
    const int wid = tid >> 5, lane = tid & 31;
    if (lane == 0) { sA[wid] = m1; sB[wid] = mz; sI[wid] = ai; }
    __syncthreads();
    if (tid == 0) {
        #pragma unroll
        for (int w = 1; w < 8; w++) {
            m1 = fmaxf(m1, sA[w]);
            if (sB[w] > mz || (sB[w] == mz && sI[w] < ai)) { mz = sB[w]; ai = sI[w]; }
        }
        sA[0] = m1; sB[0] = mz; sI[0] = ai;
    }
    __syncthreads();
    const float M1 = sA[0], MZ = sB[0];
    const int   AI = sI[0];
    __syncthreads();

    float e1 = 0.f, a1 = 0.f, e2 = 0.f;
    __half* wr = g_wscr + (size_t)pos * VV + base;
    {   // chunk A (all threads)
        float w[8];
        #pragma unroll
        for (int q = 0; q < 8; q++) {
            float t = x[q] - M1;
            float p = __expf(t);
            e1 += p; a1 += p * t;
            w[q] = __expf(z[q] - MZ);
            e2 += w[q];
        }
        __half2 h0 = __floats2half2_rn(w[0], w[1]);
        __half2 h1 = __floats2half2_rn(w[2], w[3]);
        __half2 h2 = __floats2half2_rn(w[4], w[5]);
        __half2 h3 = __floats2half2_rn(w[6], w[7]);
        uint4 pk;
        pk.x = *(uint32_t*)&h0; pk.y = *(uint32_t*)&h1;
        pk.z = *(uint32_t*)&h2; pk.w = *(uint32_t*)&h3;
        *(uint4*)(wr + iA * 4) = pk;    // default policy: keep resident in L2 for GEMM
    }
    {   // chunk B
        float w[8];
        #pragma unroll
        for (int q = 8; q < 16; q++) {
            float t = x[q] - M1;
            float p = __expf(t);
            e1 += p; a1 += p * t;
            w[q-8] = __expf(z[q] - MZ);
            e2 += w[q-8];
        }
        if (vB) {
            __half2 h0 = __floats2half2_rn(w[0], w[1]);
            __half2 h1 = __floats2half2_rn(w[2], w[3]);
            __half2 h2 = __floats2half2_rn(w[4], w[5]);
            __half2 h3 = __floats2half2_rn(w[6], w[7]);
            uint4 pk;
            pk.x = *(uint32_t*)&h0; pk.y = *(uint32_t*)&h1;
            pk.z = *(uint32_t*)&h2; pk.w = *(uint32_t*)&h3;
            *(uint4*)(wr + iB * 4) = pk;
        }
    }
    #pragma unroll
    for (int off = 16; off; off >>= 1) {
        e1 += __shfl_down_sync(FULL, e1, off);
        a1 += __shfl_down_sync(FULL, a1, off);
        e2 += __shfl_down_sync(FULL, e2, off);
    }
    __shared__ float sE1[8], sA1[8], sE2[8];
    if (lane == 0) { sE1[wid] = e1; sA1[wid] = a1; sE2[wid] = e2; }
    __syncthreads();
    if (tid == 0) {
        float E1 = 0.f, A1 = 0.f, E2 = 0.f;
        #pragma unroll
        for (int w2 = 0; w2 < 8; w2++) { E1 += sE1[w2]; A1 += sA1[w2]; E2 += sE2[w2]; }
        const int idx = pos * NSEG + seg;
        g_stA[idx] = make_float4(M1, E1, A1, 0.f);
        g_stB[idx] = make_float4(MZ, E2, __int_as_float(AI), 0.f);
    }
}

// ======== kernel 2: per-row combine (1 warp/row) ========
__global__ void k_comb(const int* __restrict__ inp_word,
                       const int* __restrict__ obf_mask,
                       const float* __restrict__ W,
                       float* __restrict__ out)
{
    const int row = blockIdx.x * 8 + (threadIdx.x >> 5);
    const int lane = threadIdx.x & 31;
    const unsigned FULL = 0xffffffffu;
    float* out_word = out;
    float* out_emb  = out + PP;
    const int iw = inp_word[row];
    const int mk = obf_mask[row];

    if (!mk) {
        if (lane == 0) { out_word[row] = (float)iw; g_ent[row] = 0.0f; g_safe[row] = 0; }
        if (lane < NSEG) g_scale[row * NSEG + lane] = 0.0f;
        for (int d = lane; d < DD; d += 32)
            out_emb[(size_t)row * DD + d] = W[(size_t)iw * DD + d];
        return;
    }

    const bool v = lane < NSEG;
    const int idx = row * NSEG + lane;
    float4 pa = v ? g_stA[idx] : make_float4(-3.0e38f, 0.f, 0.f, 0.f);
    float4 pb = v ? g_stB[idx] : make_float4(-3.0e38f, 0.f, __int_as_float(0x7fffffff), 0.f);
    float m1 = pa.x, e1 = pa.y, a1 = pa.z;
    float mz = pb.x, e2 = pb.y;
    int   ai = __float_as_int(pb.z);

    float M1 = m1, MZ = mz; int AI = ai;
    #pragma unroll
    for (int off = 16; off; off >>= 1) {
        M1 = fmaxf(M1, __shfl_xor_sync(FULL, M1, off));
        float omz = __shfl_xor_sync(FULL, MZ, off);
        int   oai = __shfl_xor_sync(FULL, AI, off);
        if (omz > MZ || (omz == MZ && oai < AI)) { MZ = omz; AI = oai; }
    }
    float E1 = v ? e1 * expf(m1 - M1) : 0.f;
    float A1 = v ? (a1 + (m1 - M1) * e1) * expf(m1 - M1) : 0.f;
    float E2 = v ? e2 * expf(mz - MZ) : 0.f;
    #pragma unroll
    for (int off = 16; off; off >>= 1) {
        E1 += __shfl_xor_sync(FULL, E1, off);
        A1 += __shfl_xor_sync(FULL, A1, off);
        E2 += __shfl_xor_sync(FULL, E2, off);
    }
    const int safe = (AI != iw) ? 1 : 0;
    if (lane == 0) {
        g_ent[row] = A1 / E1 - logf(E1);
        out_word[row] = safe ? (float)AI : 0.0f;   // UNK_ID = 0
        g_safe[row] = safe;
    }
    if (v) g_scale[idx] = safe ? (expf(mz - MZ) / E2) : 0.0f;
    if (!safe)
        for (int d = lane; d < DD; d += 32)
            out_emb[(size_t)row * DD + d] = W[d];   // UNK embedding
    // safe rows: k_red writes all 100 dims
}

// ======== kernel 3: fp16 GEMM, 3-stage cp.async, partial epilogue ========
__device__ __forceinline__ uint32_t s2u(const void* p) {
    return (uint32_t)__cvta_generic_to_shared(p);
}
__device__ __forceinline__ void ldsm4(uint32_t* r, uint32_t a) {
    asm volatile("ldmatrix.sync.aligned.m8n8.x4.shared.b16 {%0,%1,%2,%3},[%4];"
        : "=r"(r[0]), "=r"(r[1]), "=r"(r[2]), "=r"(r[3]) : "r"(a));
}
__device__ __forceinline__ void mma16816(float* c, const uint32_t* a,
                                         uint32_t b0, uint32_t b1) {
    asm volatile("mma.sync.aligned.m16n8k16.row.col.f32.f16.f16.f32 "
        "{%0,%1,%2,%3},{%4,%5,%6,%7},{%8,%9},{%0,%1,%2,%3};"
        : "+f"(c[0]), "+f"(c[1]), "+f"(c[2]), "+f"(c[3])
        : "r"(a[0]), "r"(a[1]), "r"(a[2]), "r"(a[3]), "r"(b0), "r"(b1));
}
__device__ __forceinline__ void cpa16(uint32_t s, const void* g) {
    asm volatile("cp.async.cg.shared.global [%0], [%1], 16;" :: "r"(s), "l"(g));
}
#define CP_COMMIT() asm volatile("cp.async.commit_group;")
#define CP_WAIT2()  asm volatile("cp.async.wait_group 2;")

#define ASTR 72
#define BSTR 72
#define NITER (GKSEG / GKT)    // 10

__global__ void __launch_bounds__(GTHR, 3) k_gemm(void)
{
    const int nm = g_nmask;
    const int rowBase = blockIdx.x * MT;
    if (rowBase >= nm) return;

    __shared__ __align__(16) __half As[NSTG][MT * ASTR];
    __shared__ __align__(16) __half Bs[NSTG][104 * BSTR];
    __shared__ int sRow[MT];

    const int kBase = blockIdx.y * GKSEG;
    const int tid = threadIdx.x;
    const int wid = tid >> 5, lane = tid & 31;
    const int grp = lane >> 2, tig = lane & 3;

    if (tid < MT) {
        int slot = rowBase + tid;
        sRow[tid] = g_rows[(slot < nm) ? slot : 0];
    }
    for (int i = tid; i < NSTG * 144; i += GTHR) {
        int st = i / 144, rem = i % 144;
        int r = rem / 36, c2 = rem % 36;
        ((uint32_t*)(Bs[st] + (100 + r) * BSTR))[c2] = 0u;
    }
    __syncthreads();

    float c[13][4];
    #pragma unroll
    for (int j = 0; j < 13; j++) { c[j][0]=0.f; c[j][1]=0.f; c[j][2]=0.f; c[j][3]=0.f; }

    const __half* bG = g_WhT + kBase;

    auto load_stage = [&](int st, int kc) {
        #pragma unroll
        for (int it = 0; it < 7; it++) {
            int idx = tid + it * GTHR;
            if (idx < 800) {
                int n = idx >> 3, g = idx & 7;
                cpa16(s2u(Bs[st] + n * BSTR + g * 8),
                      bG + (size_t)n * VV + kc + g * 8);
            }
        }
        #pragma unroll
        for (int it = 0; it < 4; it++) {
            int idx = tid + it * GTHR;
            int r = idx >> 3, g = idx & 7;
            cpa16(s2u(As[st] + r * ASTR + g * 8),
                  g_wscr + (size_t)sRow[r] * VV + kBase + kc + g * 8);
        }
        CP_COMMIT();
    };

    load_stage(0, 0);
    load_stage(1, GKT);
    #pragma unroll 1
    for (int i = 0; i < NITER; i++) {
        if (i + 2 < NITER) load_stage((i + 2) % NSTG, (i + 2) * GKT);
        else CP_COMMIT();
        CP_WAIT2();
        __syncthreads();

        const int s = i % NSTG;
        const int wrow = wid * 16;
        #pragma unroll
        for (int kh = 0; kh < 2; kh++) {
            const int ar = wrow + (lane & 7) + (lane & 8);
            const int ac = kh * 32 + ((lane >> 4) << 3);
            uint32_t a0[4], a1[4];
            ldsm4(a0, s2u(As[s] + ar * ASTR + ac));
            ldsm4(a1, s2u(As[s] + ar * ASTR + ac + 16));
            const int bc = kh * 32 + ((lane >> 3) << 3);
            #pragma unroll
            for (int j = 0; j < 13; j++) {
                uint32_t b[4];
                ldsm4(b, s2u(Bs[s] + (j * 8 + (lane & 7)) * BSTR + bc));
                mma16816(c[j], a0, b[0], b[1]);
                mma16816(c[j], a1, b[2], b[3]);
            }
        }
        __syncthreads();
    }

    // epilogue: scale, store partials (no atomics; .cg keeps them out of L1)
    const int sseg = blockIdx.y / 5;   // 640*5 = 3200 = stats segment
    const int sl0 = wid * 16 + grp;
    const int sl1 = sl0 + 8;
    const int r0 = sRow[sl0], r1 = sRow[sl1];
    const float s0 = g_scale[r0 * NSEG + sseg];
    const float s1 = g_scale[r1 * NSEG + sseg];
    float* p0 = &g_part[blockIdx.y][rowBase + sl0][0];
    float* p1 = &g_part[blockIdx.y][rowBase + sl1][0];
    #pragma unroll
    for (int j = 0; j < 13; j++) {
        int col = j * 8 + tig * 2;
        __stcg((float2*)(p0 + col), make_float2(c[j][0] * s0, c[j][1] * s0));
        __stcg((float2*)(p1 + col), make_float2(c[j][2] * s1, c[j][3] * s1));
    }
}

// ======== kernel 3b: parallel split-reduce into out_emb (+ ent in block 0) ====
__global__ void k_red(const int* __restrict__ obf_mask, float* __restrict__ out)
{
    const int b = blockIdx.x;
    const int tid = threadIdx.x;
    __shared__ float acc2[100];

    if (b < g_nmask) {
        const int row = g_rows[b];
        if (g_safe[row]) {
            const int d = tid % 100;
            const int sg = tid / 100;        // 0 or 1 (tid<200 active)
            float a = 0.f;
            if (tid < 200) {
                const int s0 = sg * 25;
                #pragma unroll
                for (int s = 0; s < 25; s++)
                    a += __ldcg(&g_part[s0 + s][b][d]);
            }
            if (tid >= 100 && tid < 200) acc2[d] = a;
            __syncthreads();
            if (tid < 100)
                out[PP + (size_t)row * DD + tid] = a + acc2[tid];
        }
    }
    // entropy-loss reduction (block 0 only; runs regardless of b's emb path)
    if (b == 0) {
        __shared__ float ss[256];
        __shared__ int   sc[256];
        float s = 0.f; int c = 0;
        for (int i = tid; i < PP; i += 256) {
            int m = obf_mask[i];
            if (m) { s += g_ent[i]; c++; }
        }
        ss[tid] = s; sc[tid] = c;
        __syncthreads();
        for (int o = 128; o; o >>= 1) {
            if (tid < o) { ss[tid] += ss[tid + o]; sc[tid] += sc[tid + o]; }
            __syncthreads();
        }
        if (tid == 0)
            out[PP + (size_t)PP * DD] = ss[0] / ((float)sc[0] * (float)VV);
    }
}

// ======== launch ========
extern "C" void kernel_launch(void* const* d_in, const int* in_sizes, int n_in,
                              void* d_out, int out_size)
{
    (void)in_sizes; (void)n_in; (void)out_size;
    const float* logits = (const float*)d_in[0];
    const float* gumb   = (const float*)d_in[1];
    const int*   inp    = (const int*)d_in[2];
    const int*   mask   = (const int*)d_in[3];
    const float* W      = (const float*)d_in[4];
    float* out = (float*)d_out;

    k_wconv<<<VV / TK, 256>>>(W, mask);
    dim3 gs(PP, NSEG);
    k_stats<<<gs, NT1>>>(logits, gumb, mask);
    k_comb<<<PP / 8, 256>>>(inp, mask, W, out);
    dim3 gg(PP / MT, GNSPLIT);
    k_gemm<<<gg, GTHR>>>();
    k_red<<<PP, 256>>>(mask, out);
}

// round 14
// speedup vs baseline: 1.1245x; 1.0187x over previous
#include <cuda_runtime.h>
#include <cuda_fp16.h>
#include <cstdint>

#define PP 2048
#define VV 32000
#define DD 100
#define NT1 256
#define NSEG 10
#define SEGV (VV / NSEG)          // 3200

#define MT 64
#define GKT 64
#define GNSPLIT 50
#define GKSEG (VV / GNSPLIT)      // 640
#define GTHR 128
#define NSTG 3

// ---- static device scratch (no dynamic allocation allowed) ----
__device__ __align__(16) __half g_wscr[(size_t)PP * VV];   // exp(z - mz_seg), fp16
__device__ __align__(16) __half g_WhT[(size_t)DD * VV];    // W transposed, fp16
__device__ __align__(16) float  g_part[GNSPLIT][PP][104];  // GEMM k-split partials
__device__ float4 g_stA[PP * NSEG];    // (m1, e1, a1, -)
__device__ float4 g_stB[PP * NSEG];    // (mz, e2, ai_bits, -)
__device__ float g_scale[PP * NSEG];   // exp(mz_seg - MZ)/Z2, or 0 if row inactive
__device__ float g_ent[PP];
__device__ int   g_rows[PP];           // compacted masked-row indices
__device__ int   g_safe[PP];
__device__ int   g_nmask;

// ---- L2 cache-policy helpers (sm_80+) ----
__device__ __forceinline__ uint64_t pol_evict_first() {
    uint64_t p;
    asm("createpolicy.fractional.L2::evict_first.b64 %0;" : "=l"(p));
    return p;
}
__device__ __forceinline__ uint64_t pol_evict_last() {
    uint64_t p;
    asm("createpolicy.fractional.L2::evict_last.b64 %0;" : "=l"(p));
    return p;
}
__device__ __forceinline__ float4 ld4_pol(const float4* a, uint64_t pol) {
    float4 v;
    asm("ld.global.L2::cache_hint.v4.f32 {%0,%1,%2,%3}, [%4], %5;"
        : "=f"(v.x), "=f"(v.y), "=f"(v.z), "=f"(v.w) : "l"(a), "l"(pol));
    return v;
}
__device__ __forceinline__ void st4_pol(uint4* a, uint4 v, uint64_t pol) {
    asm volatile("st.global.L2::cache_hint.v4.b32 [%0], {%1,%2,%3,%4}, %5;"
        :: "l"(a), "r"(v.x), "r"(v.y), "r"(v.z), "r"(v.w), "l"(pol) : "memory");
}
__device__ __forceinline__ void st2h_pol(__half* a, uint16_t v, uint64_t pol) {
    asm volatile("st.global.L2::cache_hint.b16 [%0], %1, %2;"
        :: "l"(a), "h"(v), "l"(pol) : "memory");
}

// -log(u + 1e-20), accurate near u==1 (where __logf's absolute error would
// corrupt the gumbel tail / argmax). Series uses exact d = 1-u for u >= 0.75.
__device__ __forceinline__ float neglog_u(float u) {
    float ue = u + 1e-20f;
    float d = 1.0f - ue;
    float s = d * (1.0f + d * (0.5f + d * (0.33333333f + d * (0.25f + d * (0.2f
             + d * (0.16666667f + d * (0.14285714f + d * (0.125f
             + d * 0.11111111f))))))));
    float l = -__logf(ue);
    return (ue >= 0.75f) ? s : l;
}
__device__ __forceinline__ float gumbel_g(float u) {
    return -__logf(neglog_u(u) + 1e-20f);
}

// ======== kernel 0: W transpose->f16  +  masked-row scan (block 0) ========
#define TK 64
__global__ void k_wconv(const float* __restrict__ W, const int* __restrict__ mask) {
    __shared__ float s[TK][DD + 1];
    const int k0 = blockIdx.x * TK;
    const int tid = threadIdx.x;
    const uint64_t pel = pol_evict_last();
    for (int idx = tid; idx < TK * DD; idx += 256) {
        int r = idx / DD, d = idx - r * DD;
        s[r][d] = W[(size_t)(k0 + r) * DD + d];
    }
    __syncthreads();
    for (int idx = tid; idx < TK * DD; idx += 256) {
        int d = idx >> 6, r = idx & 63;
        st2h_pol(&g_WhT[(size_t)d * VV + k0 + r],
                 __half_as_ushort(__float2half(s[r][d])), pel);
    }
    if (blockIdx.x == 0) {
        __shared__ int sp[256];
        int m[8], loc = 0;
        #pragma unroll
        for (int j = 0; j < 8; j++) { m[j] = mask[tid * 8 + j]; loc += m[j]; }
        sp[tid] = loc;
        __syncthreads();
        for (int off = 1; off < 256; off <<= 1) {
            int v = (tid >= off) ? sp[tid - off] : 0;
            __syncthreads();
            sp[tid] += v;
            __syncthreads();
        }
        int excl = sp[tid] - loc;
        #pragma unroll
        for (int j = 0; j < 8; j++)
            if (m[j]) g_rows[excl++] = tid * 8 + j;
        if (tid == 255) g_nmask = sp[255];
    }
}

// ======== kernel 1: per-(row,segment) stats, single memory pass ========
__global__ void k_stats(const float* __restrict__ logits,
                        const float* __restrict__ gumb,
                        const int* __restrict__ obf_mask)
{
    const int pos = blockIdx.x;
    if (!obf_mask[pos]) return;
    const int seg = blockIdx.y;
    const int tid = threadIdx.x;
    const int base = seg * SEGV;
    const float4* x4 = (const float4*)(logits + (size_t)pos * VV + base);
    const float4* u4 = (const float4*)(gumb   + (size_t)pos * VV + base);
    const uint64_t pef = pol_evict_first();
    const uint64_t pel = pol_evict_last();

    const int iA = 2 * tid;
    const int iB = 512 + 2 * tid;
    const bool vB = (tid < 144);

    float4 XV[4], UV[4];
    XV[0] = ld4_pol(x4 + iA, pef);     XV[1] = ld4_pol(x4 + iA + 1, pef);
    UV[0] = ld4_pol(u4 + iA, pef);     UV[1] = ld4_pol(u4 + iA + 1, pef);
    if (vB) {
        XV[2] = ld4_pol(x4 + iB, pef); XV[3] = ld4_pol(x4 + iB + 1, pef);
        UV[2] = ld4_pol(u4 + iB, pef); UV[3] = ld4_pol(u4 + iB + 1, pef);
    } else {
        XV[2] = make_float4(-3.0e38f, -3.0e38f, -3.0e38f, -3.0e38f);
        XV[3] = XV[2];
        UV[2] = make_float4(0.5f, 0.5f, 0.5f, 0.5f);
        UV[3] = UV[2];
    }

    float x[16], z[16];
    float m1 = -3.0e38f, mz = -3.0e38f;
    int ai = 0;
    #pragma unroll
    for (int j = 0; j < 4; j++) {
        const int e0 = base + ((j < 2) ? (iA + j) : (iB + j - 2)) * 4;
        const float* xe = &XV[j].x;
        const float* ue = &UV[j].x;
        #pragma unroll
        for (int e = 0; e < 4; e++) {
            float xv = xe[e];
            float zv = xv + gumbel_g(ue[e]);
            x[j*4+e] = xv; z[j*4+e] = zv;
            m1 = fmaxf(m1, xv);
            if (zv > mz) { mz = zv; ai = e0 + e; }
        }
    }
    const unsigned FULL = 0xffffffffu;
    #pragma unroll
    for (int off = 16; off; off >>= 1) {
        m1 = fmaxf(m1, __shfl_down_sync(FULL, m1, off));
        float oz = __shfl_down_sync(FULL, mz, off);
        int   oi = __shfl_down_sync(FULL, ai, off);
        if (oz > mz || (oz == mz && oi < ai)) { mz = oz; ai = oi; }
    }
    __shared__ float sA[8], sB[8];
    __shared__ int   sI[8];
    const int wid = tid >> 5, lane = tid & 31;
    if (lane == 0) { sA[wid] = m1; sB[wid] = mz; sI[wid] = ai; }
    __syncthreads();
    if (tid == 0) {
        #pragma unroll
        for (int w = 1; w < 8; w++) {
            m1 = fmaxf(m1, sA[w]);
            if (sB[w] > mz || (sB[w] == mz && sI[w] < ai)) { mz = sB[w]; ai = sI[w]; }
        }
        sA[0] = m1; sB[0] = mz; sI[0] = ai;
    }
    __syncthreads();
    const float M1 = sA[0], MZ = sB[0];
    const int   AI = sI[0];

    float e1 = 0.f, a1 = 0.f, e2 = 0.f;
    __half* wr = g_wscr + (size_t)pos * VV + base;
    {   // chunk A (all threads)
        float w[8];
        #pragma unroll
        for (int q = 0; q < 8; q++) {
            float t = x[q] - M1;
            float p = __expf(t);
            e1 += p; a1 += p * t;
            w[q] = __expf(z[q] - MZ);
            e2 += w[q];
        }
        __half2 h0 = __floats2half2_rn(w[0], w[1]);
        __half2 h1 = __floats2half2_rn(w[2], w[3]);
        __half2 h2 = __floats2half2_rn(w[4], w[5]);
        __half2 h3 = __floats2half2_rn(w[6], w[7]);
        uint4 pk;
        pk.x = *(uint32_t*)&h0; pk.y = *(uint32_t*)&h1;
        pk.z = *(uint32_t*)&h2; pk.w = *(uint32_t*)&h3;
        st4_pol((uint4*)(wr + iA * 4), pk, pel);   // pin for GEMM read
    }
    {   // chunk B
        float w[8];
        #pragma unroll
        for (int q = 8; q < 16; q++) {
            float t = x[q] - M1;
            float p = __expf(t);
            e1 += p; a1 += p * t;
            w[q-8] = __expf(z[q] - MZ);
            e2 += w[q-8];
        }
        if (vB) {
            __half2 h0 = __floats2half2_rn(w[0], w[1]);
            __half2 h1 = __floats2half2_rn(w[2], w[3]);
            __half2 h2 = __floats2half2_rn(w[4], w[5]);
            __half2 h3 = __floats2half2_rn(w[6], w[7]);
            uint4 pk;
            pk.x = *(uint32_t*)&h0; pk.y = *(uint32_t*)&h1;
            pk.z = *(uint32_t*)&h2; pk.w = *(uint32_t*)&h3;
            st4_pol((uint4*)(wr + iB * 4), pk, pel);
        }
    }
    #pragma unroll
    for (int off = 16; off; off >>= 1) {
        e1 += __shfl_down_sync(FULL, e1, off);
        a1 += __shfl_down_sync(FULL, a1, off);
        e2 += __shfl_down_sync(FULL, e2, off);
    }
    __shared__ float sE1[8], sA1[8], sE2[8];
    if (lane == 0) { sE1[wid] = e1; sA1[wid] = a1; sE2[wid] = e2; }
    __syncthreads();
    if (tid == 0) {
        float E1 = 0.f, A1 = 0.f, E2 = 0.f;
        #pragma unroll
        for (int w2 = 0; w2 < 8; w2++) { E1 += sE1[w2]; A1 += sA1[w2]; E2 += sE2[w2]; }
        const int idx = pos * NSEG + seg;
        g_stA[idx] = make_float4(M1, E1, A1, 0.f);
        g_stB[idx] = make_float4(MZ, E2, __int_as_float(AI), 0.f);
    }
}

// ======== kernel 2: per-row combine (1 warp/row) ========
__global__ void k_comb(const int* __restrict__ inp_word,
                       const int* __restrict__ obf_mask,
                       const float* __restrict__ W,
                       float* __restrict__ out)
{
    const int row = blockIdx.x * 8 + (threadIdx.x >> 5);
    const int lane = threadIdx.x & 31;
    const unsigned FULL = 0xffffffffu;
    float* out_word = out;
    float* out_emb  = out + PP;
    const int iw = inp_word[row];
    const int mk = obf_mask[row];

    if (!mk) {
        if (lane == 0) { out_word[row] = (float)iw; g_ent[row] = 0.0f; g_safe[row] = 0; }
        if (lane < NSEG) g_scale[row * NSEG + lane] = 0.0f;
        for (int d = lane; d < DD; d += 32)
            out_emb[(size_t)row * DD + d] = W[(size_t)iw * DD + d];
        return;
    }

    const bool v = lane < NSEG;
    const int idx = row * NSEG + lane;
    float4 pa = v ? g_stA[idx] : make_float4(-3.0e38f, 0.f, 0.f, 0.f);
    float4 pb = v ? g_stB[idx] : make_float4(-3.0e38f, 0.f, __int_as_float(0x7fffffff), 0.f);
    float m1 = pa.x, e1 = pa.y, a1 = pa.z;
    float mz = pb.x, e2 = pb.y;
    int   ai = __float_as_int(pb.z);

    float M1 = m1, MZ = mz; int AI = ai;
    #pragma unroll
    for (int off = 16; off; off >>= 1) {
        M1 = fmaxf(M1, __shfl_xor_sync(FULL, M1, off));
        float omz = __shfl_xor_sync(FULL, MZ, off);
        int   oai = __shfl_xor_sync(FULL, AI, off);
        if (omz > MZ || (omz == MZ && oai < AI)) { MZ = omz; AI = oai; }
    }
    float E1 = v ? e1 * expf(m1 - M1) : 0.f;
    float A1 = v ? (a1 + (m1 - M1) * e1) * expf(m1 - M1) : 0.f;
    float E2 = v ? e2 * expf(mz - MZ) : 0.f;
    #pragma unroll
    for (int off = 16; off; off >>= 1) {
        E1 += __shfl_xor_sync(FULL, E1, off);
        A1 += __shfl_xor_sync(FULL, A1, off);
        E2 += __shfl_xor_sync(FULL, E2, off);
    }
    const int safe = (AI != iw) ? 1 : 0;
    if (lane == 0) {
        g_ent[row] = A1 / E1 - logf(E1);
        out_word[row] = safe ? (float)AI : 0.0f;   // UNK_ID = 0
        g_safe[row] = safe;
    }
    if (v) g_scale[idx] = safe ? (expf(mz - MZ) / E2) : 0.0f;
    if (!safe)
        for (int d = lane; d < DD; d += 32)
            out_emb[(size_t)row * DD + d] = W[d];   // UNK embedding
    // safe rows: k_red writes all 100 dims
}

// ======== kernel 3: fp16 GEMM, 3-stage cp.async, partial epilogue ========
__device__ __forceinline__ uint32_t s2u(const void* p) {
    return (uint32_t)__cvta_generic_to_shared(p);
}
__device__ __forceinline__ void ldsm4(uint32_t* r, uint32_t a) {
    asm volatile("ldmatrix.sync.aligned.m8n8.x4.shared.b16 {%0,%1,%2,%3},[%4];"
        : "=r"(r[0]), "=r"(r[1]), "=r"(r[2]), "=r"(r[3]) : "r"(a));
}
__device__ __forceinline__ void mma16816(float* c, const uint32_t* a,
                                         uint32_t b0, uint32_t b1) {
    asm volatile("mma.sync.aligned.m16n8k16.row.col.f32.f16.f16.f32 "
        "{%0,%1,%2,%3},{%4,%5,%6,%7},{%8,%9},{%0,%1,%2,%3};"
        : "+f"(c[0]), "+f"(c[1]), "+f"(c[2]), "+f"(c[3])
        : "r"(a[0]), "r"(a[1]), "r"(a[2]), "r"(a[3]), "r"(b0), "r"(b1));
}
__device__ __forceinline__ void cpa16_pol(uint32_t s, const void* g, uint64_t pol) {
    asm volatile("cp.async.cg.shared.global.L2::cache_hint [%0], [%1], 16, %2;"
        :: "r"(s), "l"(g), "l"(pol));
}
#define CP_COMMIT() asm volatile("cp.async.commit_group;")
#define CP_WAIT2()  asm volatile("cp.async.wait_group 2;")

#define ASTR 72
#define BSTR 72
#define NITER (GKSEG / GKT)    // 10

__global__ void __launch_bounds__(GTHR, 3) k_gemm(void)
{
    const int nm = g_nmask;
    const int rowBase = blockIdx.x * MT;
    if (rowBase >= nm) return;

    __shared__ __align__(16) __half As[NSTG][MT * ASTR];
    __shared__ __align__(16) __half Bs[NSTG][104 * BSTR];
    __shared__ int sRow[MT];

    const int kBase = blockIdx.y * GKSEG;
    const int tid = threadIdx.x;
    const int wid = tid >> 5, lane = tid & 31;
    const int grp = lane >> 2, tig = lane & 3;
    const uint64_t pef = pol_evict_first();
    const uint64_t pel = pol_evict_last();

    if (tid < MT) {
        int slot = rowBase + tid;
        sRow[tid] = g_rows[(slot < nm) ? slot : 0];
    }
    for (int i = tid; i < NSTG * 144; i += GTHR) {
        int st = i / 144, rem = i % 144;
        int r = rem / 36, c2 = rem % 36;
        ((uint32_t*)(Bs[st] + (100 + r) * BSTR))[c2] = 0u;
    }
    __syncthreads();

    float c[13][4];
    #pragma unroll
    for (int j = 0; j < 13; j++) { c[j][0]=0.f; c[j][1]=0.f; c[j][2]=0.f; c[j][3]=0.f; }

    const __half* bG = g_WhT + kBase;

    auto load_stage = [&](int st, int kc) {
        #pragma unroll
        for (int it = 0; it < 7; it++) {
            int idx = tid + it * GTHR;
            if (idx < 800) {
                int n = idx >> 3, g = idx & 7;
                cpa16_pol(s2u(Bs[st] + n * BSTR + g * 8),
                          bG + (size_t)n * VV + kc + g * 8, pel);
            }
        }
        #pragma unroll
        for (int it = 0; it < 4; it++) {
            int idx = tid + it * GTHR;
            int r = idx >> 3, g = idx & 7;
            cpa16_pol(s2u(As[st] + r * ASTR + g * 8),
                      g_wscr + (size_t)sRow[r] * VV + kBase + kc + g * 8, pef);
        }
        CP_COMMIT();
    };

    load_stage(0, 0);
    load_stage(1, GKT);
    #pragma unroll 1
    for (int i = 0; i < NITER; i++) {
        if (i + 2 < NITER) load_stage((i + 2) % NSTG, (i + 2) * GKT);
        else CP_COMMIT();
        CP_WAIT2();
        __syncthreads();

        const int s = i % NSTG;
        const int wrow = wid * 16;
        #pragma unroll
        for (int kh = 0; kh < 2; kh++) {
            const int ar = wrow + (lane & 7) + (lane & 8);
            const int ac = kh * 32 + ((lane >> 4) << 3);
            uint32_t a0[4], a1[4];
            ldsm4(a0, s2u(As[s] + ar * ASTR + ac));
            ldsm4(a1, s2u(As[s] + ar * ASTR + ac + 16));
            const int bc = kh * 32 + ((lane >> 3) << 3);
            #pragma unroll
            for (int j = 0; j < 13; j++) {
                uint32_t b[4];
                ldsm4(b, s2u(Bs[s] + (j * 8 + (lane & 7)) * BSTR + bc));
                mma16816(c[j], a0, b[0], b[1]);
                mma16816(c[j], a1, b[2], b[3]);
            }
        }
        __syncthreads();
    }

    // epilogue: scale, store partials (no atomics; .cg keeps them out of L1)
    const int sseg = blockIdx.y / 5;   // 640*5 = 3200 = stats segment
    const int sl0 = wid * 16 + grp;
    const int sl1 = sl0 + 8;
    const int r0 = sRow[sl0], r1 = sRow[sl1];
    const float s0 = g_scale[r0 * NSEG + sseg];
    const float s1 = g_scale[r1 * NSEG + sseg];
    float* p0 = &g_part[blockIdx.y][rowBase + sl0][0];
    float* p1 = &g_part[blockIdx.y][rowBase + sl1][0];
    #pragma unroll
    for (int j = 0; j < 13; j++) {
        int col = j * 8 + tig * 2;
        __stcg((float2*)(p0 + col), make_float2(c[j][0] * s0, c[j][1] * s0));
        __stcg((float2*)(p1 + col), make_float2(c[j][2] * s1, c[j][3] * s1));
    }
}

// ======== kernel 3b: parallel split-reduce into out_emb (+ ent in block 0) ====
__global__ void k_red(const int* __restrict__ obf_mask, float* __restrict__ out)
{
    const int b = blockIdx.x;
    const int tid = threadIdx.x;
    __shared__ float acc2[100];

    if (b < g_nmask) {
        const int row = g_rows[b];
        if (g_safe[row]) {
            const int d = tid % 100;
            const int sg = tid / 100;        // 0 or 1 (tid<200 active)
            float a = 0.f;
            if (tid < 200) {
                const int s0 = sg * 25;
                #pragma unroll
                for (int s = 0; s < 25; s++)
                    a += __ldcg(&g_part[s0 + s][b][d]);
            }
            if (tid >= 100 && tid < 200) acc2[d] = a;
            __syncthreads();
            if (tid < 100)
                out[PP + (size_t)row * DD + tid] = a + acc2[tid];
        }
    }
    // entropy-loss reduction (block 0 only; runs regardless of b's emb path)
    if (b == 0) {
        __shared__ float ss[256];
        __shared__ int   sc[256];
        float s = 0.f; int c = 0;
        for (int i = tid; i < PP; i += 256) {
            int m = obf_mask[i];
            if (m) { s += g_ent[i]; c++; }
        }
        ss[tid] = s; sc[tid] = c;
        __syncthreads();
        for (int o = 128; o; o >>= 1) {
            if (tid < o) { ss[tid] += ss[tid + o]; sc[tid] += sc[tid + o]; }
            __syncthreads();
        }
        if (tid == 0)
            out[PP + (size_t)PP * DD] = ss[0] / ((float)sc[0] * (float)VV);
    }
}

// ======== launch ========
extern "C" void kernel_launch(void* const* d_in, const int* in_sizes, int n_in,
                              void* d_out, int out_size)
{
    (void)in_sizes; (void)n_in; (void)out_size;
    const float* logits = (const float*)d_in[0];
    const float* gumb   = (const float*)d_in[1];
    const int*   inp    = (const int*)d_in[2];
    const int*   mask   = (const int*)d_in[3];
    const float* W      = (const float*)d_in[4];
    float* out = (float*)d_out;

    k_wconv<<<VV / TK, 256>>>(W, mask);
    dim3 gs(PP, NSEG);
    k_stats<<<gs, NT1>>>(logits, gumb, mask);
    k_comb<<<PP / 8, 256>>>(inp, mask, W, out);
    dim3 gg(PP / MT, GNSPLIT);
    k_gemm<<<gg, GTHR>>>();
    k_red<<<PP, 256>>>(mask, out);
}

// round 16
// speedup vs baseline: 1.1415x; 1.0151x over previous
#include <cuda_runtime.h>
#include <cuda_fp16.h>
#include <cstdint>

#define PP 2048
#define VV 32000
#define DD 100
#define NT1 256
#define NSEG 10
#define SEGV (VV / NSEG)          // 3200

#define MT 64
#define GKT 64
#define GNSPLIT 50
#define GKSEG (VV / GNSPLIT)      // 640
#define GTHR 128
#define NSTG 3

// ---- static device scratch (no dynamic allocation allowed) ----
__device__ __align__(16) __half g_wscr[(size_t)PP * VV];   // exp(z - mz_seg), fp16
__device__ __align__(16) __half g_WhT[(size_t)DD * VV];    // W transposed, fp16
__device__ __align__(16) float  g_part[GNSPLIT][PP][104];  // GEMM k-split partials (unscaled)
__device__ float4 g_stA[PP * NSEG];    // (m1, e1, a1, -)
__device__ float4 g_stB[PP * NSEG];    // (mz, e2, ai_bits, -)
__device__ float g_scale[PP * NSEG];   // exp(mz_seg - MZ)/Z2, or 0 if row inactive
__device__ float g_ent[PP];
__device__ int   g_rows[PP];           // compacted masked-row indices
__device__ int   g_safe[PP];
__device__ int   g_nmask;

// ---- L2 cache-policy helpers (sm_80+) ----
__device__ __forceinline__ uint64_t pol_evict_first() {
    uint64_t p;
    asm("createpolicy.fractional.L2::evict_first.b64 %0;" : "=l"(p));
    return p;
}
__device__ __forceinline__ uint64_t pol_evict_last() {
    uint64_t p;
    asm("createpolicy.fractional.L2::evict_last.b64 %0;" : "=l"(p));
    return p;
}
__device__ __forceinline__ float4 ld4_pol(const float4* a, uint64_t pol) {
    float4 v;
    asm("ld.global.L2::cache_hint.v4.f32 {%0,%1,%2,%3}, [%4], %5;"
        : "=f"(v.x), "=f"(v.y), "=f"(v.z), "=f"(v.w) : "l"(a), "l"(pol));
    return v;
}
__device__ __forceinline__ void st4_pol(uint4* a, uint4 v, uint64_t pol) {
    asm volatile("st.global.L2::cache_hint.v4.b32 [%0], {%1,%2,%3,%4}, %5;"
        :: "l"(a), "r"(v.x), "r"(v.y), "r"(v.z), "r"(v.w), "l"(pol) : "memory");
}
__device__ __forceinline__ void st2h_pol(__half* a, uint16_t v, uint64_t pol) {
    asm volatile("st.global.L2::cache_hint.b16 [%0], %1, %2;"
        :: "l"(a), "h"(v), "l"(pol) : "memory");
}

// -log(u + 1e-20), accurate near u==1 (where __logf's absolute error would
// corrupt the gumbel tail / argmax). Series uses exact d = 1-u for u >= 0.75.
__device__ __forceinline__ float neglog_u(float u) {
    float ue = u + 1e-20f;
    float d = 1.0f - ue;
    float s = d * (1.0f + d * (0.5f + d * (0.33333333f + d * (0.25f + d * (0.2f
             + d * (0.16666667f + d * (0.14285714f + d * (0.125f
             + d * 0.11111111f))))))));
    float l = -__logf(ue);
    return (ue >= 0.75f) ? s : l;
}
__device__ __forceinline__ float gumbel_g(float u) {
    return -__logf(neglog_u(u) + 1e-20f);
}

// ======== kernel 0: W transpose->f16  +  masked-row scan (block 0) ========
#define TK 64
__global__ void k_wconv(const float* __restrict__ W, const int* __restrict__ mask) {
    __shared__ float s[TK][DD + 1];
    const int k0 = blockIdx.x * TK;
    const int tid = threadIdx.x;
    const uint64_t pel = pol_evict_last();
    for (int idx = tid; idx < TK * DD; idx += 256) {
        int r = idx / DD, d = idx - r * DD;
        s[r][d] = W[(size_t)(k0 + r) * DD + d];
    }
    __syncthreads();
    for (int idx = tid; idx < TK * DD; idx += 256) {
        int d = idx >> 6, r = idx & 63;
        st2h_pol(&g_WhT[(size_t)d * VV + k0 + r],
                 __half_as_ushort(__float2half(s[r][d])), pel);
    }
    if (blockIdx.x == 0) {
        __shared__ int sp[256];
        int m[8], loc = 0;
        #pragma unroll
        for (int j = 0; j < 8; j++) { m[j] = mask[tid * 8 + j]; loc += m[j]; }
        sp[tid] = loc;
        __syncthreads();
        for (int off = 1; off < 256; off <<= 1) {
            int v = (tid >= off) ? sp[tid - off] : 0;
            __syncthreads();
            sp[tid] += v;
            __syncthreads();
        }
        int excl = sp[tid] - loc;
        #pragma unroll
        for (int j = 0; j < 8; j++)
            if (m[j]) g_rows[excl++] = tid * 8 + j;
        if (tid == 255) g_nmask = sp[255];
    }
}

// ======== kernel 1: per-(row,segment) stats, single memory pass ========
__global__ void k_stats(const float* __restrict__ logits,
                        const float* __restrict__ gumb,
                        const int* __restrict__ obf_mask,
                        int segBase)
{
    const int pos = blockIdx.x;
    if (!obf_mask[pos]) return;
    const int seg = blockIdx.y + segBase;
    const int tid = threadIdx.x;
    const int base = seg * SEGV;
    const float4* x4 = (const float4*)(logits + (size_t)pos * VV + base);
    const float4* u4 = (const float4*)(gumb   + (size_t)pos * VV + base);
    const uint64_t pef = pol_evict_first();
    const uint64_t pel = pol_evict_last();

    const int iA = 2 * tid;
    const int iB = 512 + 2 * tid;
    const bool vB = (tid < 144);

    float4 XV[4], UV[4];
    XV[0] = ld4_pol(x4 + iA, pef);     XV[1] = ld4_pol(x4 + iA + 1, pef);
    UV[0] = ld4_pol(u4 + iA, pef);     UV[1] = ld4_pol(u4 + iA + 1, pef);
    if (vB) {
        XV[2] = ld4_pol(x4 + iB, pef); XV[3] = ld4_pol(x4 + iB + 1, pef);
        UV[2] = ld4_pol(u4 + iB, pef); UV[3] = ld4_pol(u4 + iB + 1, pef);
    } else {
        XV[2] = make_float4(-3.0e38f, -3.0e38f, -3.0e38f, -3.0e38f);
        XV[3] = XV[2];
        UV[2] = make_float4(0.5f, 0.5f, 0.5f, 0.5f);
        UV[3] = UV[2];
    }

    float x[16], z[16];
    float m1 = -3.0e38f, mz = -3.0e38f;
    int ai = 0;
    #pragma unroll
    for (int j = 0; j < 4; j++) {
        const int e0 = base + ((j < 2) ? (iA + j) : (iB + j - 2)) * 4;
        const float* xe = &XV[j].x;
        const float* ue = &UV[j].x;
        #pragma unroll
        for (int e = 0; e < 4; e++) {
            float xv = xe[e];
            float zv = xv + gumbel_g(ue[e]);
            x[j*4+e] = xv; z[j*4+e] = zv;
            m1 = fmaxf(m1, xv);
            if (zv > mz) { mz = zv; ai = e0 + e; }
        }
    }
    const unsigned FULL = 0xffffffffu;
    #pragma unroll
    for (int off = 16; off; off >>= 1) {
        m1 = fmaxf(m1, __shfl_down_sync(FULL, m1, off));
        float oz = __shfl_down_sync(FULL, mz, off);
        int   oi = __shfl_down_sync(FULL, ai, off);
        if (oz > mz || (oz == mz && oi < ai)) { mz = oz; ai = oi; }
    }
    __shared__ float sA[8], sB[8];
    __shared__ int   sI[8];
    const int wid = tid >> 5, lane = tid & 31;
    if (lane == 0) { sA[wid] = m1; sB[wid] = mz; sI[wid] = ai; }
    __syncthreads();
    if (tid == 0) {
        #pragma unroll
        for (int w = 1; w < 8; w++) {
            m1 = fmaxf(m1, sA[w]);
            if (sB[w] > mz || (sB[w] == mz && sI[w] < ai)) { mz = sB[w]; ai = sI[w]; }
        }
        sA[0] = m1; sB[0] = mz; sI[0] = ai;
    }
    __syncthreads();
    const float M1 = sA[0], MZ = sB[0];
    const int   AI = sI[0];

    float e1 = 0.f, a1 = 0.f, e2 = 0.f;
    __half* wr = g_wscr + (size_t)pos * VV + base;
    {   // chunk A (all threads)
        float w[8];
        #pragma unroll
        for (int q = 0; q < 8; q++) {
            float t = x[q] - M1;
            float p = __expf(t);
            e1 += p; a1 += p * t;
            w[q] = __expf(z[q] - MZ);
            e2 += w[q];
        }
        __half2 h0 = __floats2half2_rn(w[0], w[1]);
        __half2 h1 = __floats2half2_rn(w[2], w[3]);
        __half2 h2 = __floats2half2_rn(w[4], w[5]);
        __half2 h3 = __floats2half2_rn(w[6], w[7]);
        uint4 pk;
        pk.x = *(uint32_t*)&h0; pk.y = *(uint32_t*)&h1;
        pk.z = *(uint32_t*)&h2; pk.w = *(uint32_t*)&h3;
        st4_pol((uint4*)(wr + iA * 4), pk, pel);
    }
    {   // chunk B
        float w[8];
        #pragma unroll
        for (int q = 8; q < 16; q++) {
            float t = x[q] - M1;
            float p = __expf(t);
            e1 += p; a1 += p * t;
            w[q-8] = __expf(z[q] - MZ);
            e2 += w[q-8];
        }
        if (vB) {
            __half2 h0 = __floats2half2_rn(w[0], w[1]);
            __half2 h1 = __floats2half2_rn(w[2], w[3]);
            __half2 h2 = __floats2half2_rn(w[4], w[5]);
            __half2 h3 = __floats2half2_rn(w[6], w[7]);
            uint4 pk;
            pk.x = *(uint32_t*)&h0; pk.y = *(uint32_t*)&h1;
            pk.z = *(uint32_t*)&h2; pk.w = *(uint32_t*)&h3;
            st4_pol((uint4*)(wr + iB * 4), pk, pel);
        }
    }
    #pragma unroll
    for (int off = 16; off; off >>= 1) {
        e1 += __shfl_down_sync(FULL, e1, off);
        a1 += __shfl_down_sync(FULL, a1, off);
        e2 += __shfl_down_sync(FULL, e2, off);
    }
    __shared__ float sE1[8], sA1[8], sE2[8];
    if (lane == 0) { sE1[wid] = e1; sA1[wid] = a1; sE2[wid] = e2; }
    __syncthreads();
    if (tid == 0) {
        float E1 = 0.f, A1 = 0.f, E2 = 0.f;
        #pragma unroll
        for (int w2 = 0; w2 < 8; w2++) { E1 += sE1[w2]; A1 += sA1[w2]; E2 += sE2[w2]; }
        const int idx = pos * NSEG + seg;
        g_stA[idx] = make_float4(M1, E1, A1, 0.f);
        g_stB[idx] = make_float4(MZ, E2, __int_as_float(AI), 0.f);
    }
}

// ======== kernel 2: per-row combine (1 warp/row) ========
__global__ void k_comb(const int* __restrict__ inp_word,
                       const int* __restrict__ obf_mask,
                       const float* __restrict__ W,
                       float* __restrict__ out)
{
    const int row = blockIdx.x * 8 + (threadIdx.x >> 5);
    const int lane = threadIdx.x & 31;
    const unsigned FULL = 0xffffffffu;
    float* out_word = out;
    float* out_emb  = out + PP;
    const int iw = inp_word[row];
    const int mk = obf_mask[row];

    if (!mk) {
        if (lane == 0) { out_word[row] = (float)iw; g_ent[row] = 0.0f; g_safe[row] = 0; }
        if (lane < NSEG) g_scale[row * NSEG + lane] = 0.0f;
        for (int d = lane; d < DD; d += 32)
            out_emb[(size_t)row * DD + d] = W[(size_t)iw * DD + d];
        return;
    }

    const bool v = lane < NSEG;
    const int idx = row * NSEG + lane;
    float4 pa = v ? g_stA[idx] : make_float4(-3.0e38f, 0.f, 0.f, 0.f);
    float4 pb = v ? g_stB[idx] : make_float4(-3.0e38f, 0.f, __int_as_float(0x7fffffff), 0.f);
    float m1 = pa.x, e1 = pa.y, a1 = pa.z;
    float mz = pb.x, e2 = pb.y;
    int   ai = __float_as_int(pb.z);

    float M1 = m1, MZ = mz; int AI = ai;
    #pragma unroll
    for (int off = 16; off; off >>= 1) {
        M1 = fmaxf(M1, __shfl_xor_sync(FULL, M1, off));
        float omz = __shfl_xor_sync(FULL, MZ, off);
        int   oai = __shfl_xor_sync(FULL, AI, off);
        if (omz > MZ || (omz == MZ && oai < AI)) { MZ = omz; AI = oai; }
    }
    float E1 = v ? e1 * expf(m1 - M1) : 0.f;
    float A1 = v ? (a1 + (m1 - M1) * e1) * expf(m1 - M1) : 0.f;
    float E2 = v ? e2 * expf(mz - MZ) : 0.f;
    #pragma unroll
    for (int off = 16; off; off >>= 1) {
        E1 += __shfl_xor_sync(FULL, E1, off);
        A1 += __shfl_xor_sync(FULL, A1, off);
        E2 += __shfl_xor_sync(FULL, E2, off);
    }
    const int safe = (AI != iw) ? 1 : 0;
    if (lane == 0) {
        g_ent[row] = A1 / E1 - logf(E1);
        out_word[row] = safe ? (float)AI : 0.0f;   // UNK_ID = 0
        g_safe[row] = safe;
    }
    if (v) g_scale[idx] = safe ? (expf(mz - MZ) / E2) : 0.0f;
    if (!safe)
        for (int d = lane; d < DD; d += 32)
            out_emb[(size_t)row * DD + d] = W[d];   // UNK embedding
    // safe rows: k_red writes all 100 dims
}

// ======== kernel 3: fp16 GEMM, 3-stage cp.async, UNscaled partial epilogue ====
__device__ __forceinline__ uint32_t s2u(const void* p) {
    return (uint32_t)__cvta_generic_to_shared(p);
}
__device__ __forceinline__ void ldsm4(uint32_t* r, uint32_t a) {
    asm volatile("ldmatrix.sync.aligned.m8n8.x4.shared.b16 {%0,%1,%2,%3},[%4];"
        : "=r"(r[0]), "=r"(r[1]), "=r"(r[2]), "=r"(r[3]) : "r"(a));
}
__device__ __forceinline__ void mma16816(float* c, const uint32_t* a,
                                         uint32_t b0, uint32_t b1) {
    asm volatile("mma.sync.aligned.m16n8k16.row.col.f32.f16.f16.f32 "
        "{%0,%1,%2,%3},{%4,%5,%6,%7},{%8,%9},{%0,%1,%2,%3};"
        : "+f"(c[0]), "+f"(c[1]), "+f"(c[2]), "+f"(c[3])
        : "r"(a[0]), "r"(a[1]), "r"(a[2]), "r"(a[3]), "r"(b0), "r"(b1));
}
__device__ __forceinline__ void cpa16_pol(uint32_t s, const void* g, uint64_t pol) {
    asm volatile("cp.async.cg.shared.global.L2::cache_hint [%0], [%1], 16, %2;"
        :: "r"(s), "l"(g), "l"(pol));
}
#define CP_COMMIT() asm volatile("cp.async.commit_group;")
#define CP_WAIT2()  asm volatile("cp.async.wait_group 2;")

#define ASTR 72
#define BSTR 72
#define NITER (GKSEG / GKT)    // 10

__global__ void __launch_bounds__(GTHR, 3) k_gemm(int yBase)
{
    const int nm = g_nmask;
    const int rowBase = blockIdx.x * MT;
    if (rowBase >= nm) return;

    __shared__ __align__(16) __half As[NSTG][MT * ASTR];
    __shared__ __align__(16) __half Bs[NSTG][104 * BSTR];
    __shared__ int sRow[MT];

    const int ys = blockIdx.y + yBase;
    const int kBase = ys * GKSEG;
    const int tid = threadIdx.x;
    const int wid = tid >> 5, lane = tid & 31;
    const int grp = lane >> 2, tig = lane & 3;
    const uint64_t pef = pol_evict_first();
    const uint64_t pel = pol_evict_last();

    if (tid < MT) {
        int slot = rowBase + tid;
        sRow[tid] = g_rows[(slot < nm) ? slot : 0];
    }
    for (int i = tid; i < NSTG * 144; i += GTHR) {
        int st = i / 144, rem = i % 144;
        int r = rem / 36, c2 = rem % 36;
        ((uint32_t*)(Bs[st] + (100 + r) * BSTR))[c2] = 0u;
    }
    __syncthreads();

    float c[13][4];
    #pragma unroll
    for (int j = 0; j < 13; j++) { c[j][0]=0.f; c[j][1]=0.f; c[j][2]=0.f; c[j][3]=0.f; }

    const __half* bG = g_WhT + kBase;

    auto load_stage = [&](int st, int kc) {
        #pragma unroll
        for (int it = 0; it < 7; it++) {
            int idx = tid + it * GTHR;
            if (idx < 800) {
                int n = idx >> 3, g = idx & 7;
                cpa16_pol(s2u(Bs[st] + n * BSTR + g * 8),
                          bG + (size_t)n * VV + kc + g * 8, pel);
            }
        }
        #pragma unroll
        for (int it = 0; it < 4; it++) {
            int idx = tid + it * GTHR;
            int r = idx >> 3, g = idx & 7;
            cpa16_pol(s2u(As[st] + r * ASTR + g * 8),
                      g_wscr + (size_t)sRow[r] * VV + kBase + kc + g * 8, pef);
        }
        CP_COMMIT();
    };

    load_stage(0, 0);
    load_stage(1, GKT);
    #pragma unroll 1
    for (int i = 0; i < NITER; i++) {
        if (i + 2 < NITER) load_stage((i + 2) % NSTG, (i + 2) * GKT);
        else CP_COMMIT();
        CP_WAIT2();
        __syncthreads();

        const int s = i % NSTG;
        const int wrow = wid * 16;
        #pragma unroll
        for (int kh = 0; kh < 2; kh++) {
            const int ar = wrow + (lane & 7) + (lane & 8);
            const int ac = kh * 32 + ((lane >> 4) << 3);
            uint32_t a0[4], a1[4];
            ldsm4(a0, s2u(As[s] + ar * ASTR + ac));
            ldsm4(a1, s2u(As[s] + ar * ASTR + ac + 16));
            const int bc = kh * 32 + ((lane >> 3) << 3);
            #pragma unroll
            for (int j = 0; j < 13; j++) {
                uint32_t b[4];
                ldsm4(b, s2u(Bs[s] + (j * 8 + (lane & 7)) * BSTR + bc));
                mma16816(c[j], a0, b[0], b[1]);
                mma16816(c[j], a1, b[2], b[3]);
            }
        }
        __syncthreads();
    }

    // epilogue: store UNscaled partials (scale applied in k_red)
    const int sl0 = wid * 16 + grp;
    const int sl1 = sl0 + 8;
    float* p0 = &g_part[ys][rowBase + sl0][0];
    float* p1 = &g_part[ys][rowBase + sl1][0];
    #pragma unroll
    for (int j = 0; j < 13; j++) {
        int col = j * 8 + tig * 2;
        __stcg((float2*)(p0 + col), make_float2(c[j][0], c[j][1]));
        __stcg((float2*)(p1 + col), make_float2(c[j][2], c[j][3]));
    }
}

// ======== kernel 3b: scaled split-reduce into out_emb (+ ent in block 0) ====
__global__ void k_red(const int* __restrict__ obf_mask, float* __restrict__ out)
{
    const int b = blockIdx.x;
    const int tid = threadIdx.x;
    __shared__ float acc2[100];

    if (b < g_nmask) {
        const int row = g_rows[b];
        if (g_safe[row]) {
            const int d = tid % 100;
            const int sg = tid / 100;        // 0 or 1 (tid<200 active)
            float a = 0.f;
            if (tid < 200) {
                #pragma unroll
                for (int g = 0; g < 5; g++) {
                    const float sc = g_scale[row * NSEG + sg * 5 + g];
                    const int s0 = sg * 25 + g * 5;
                    #pragma unroll
                    for (int i = 0; i < 5; i++)
                        a += __ldcg(&g_part[s0 + i][b][d]) * sc;
                }
            }
            if (tid >= 100 && tid < 200) acc2[d] = a;
            __syncthreads();
            if (tid < 100)
                out[PP + (size_t)row * DD + tid] = a + acc2[tid];
        }
    }
    // entropy-loss reduction (block 0 only)
    if (b == 0) {
        __shared__ float ss[256];
        __shared__ int   sc[256];
        float s = 0.f; int c = 0;
        for (int i = tid; i < PP; i += 256) {
            int m = obf_mask[i];
            if (m) { s += g_ent[i]; c++; }
        }
        ss[tid] = s; sc[tid] = c;
        __syncthreads();
        for (int o = 128; o; o >>= 1) {
            if (tid < o) { ss[tid] += ss[tid + o]; sc[tid] += sc[tid + o]; }
            __syncthreads();
        }
        if (tid == 0)
            out[PP + (size_t)PP * DD] = ss[0] / ((float)sc[0] * (float)VV);
    }
}

// ======== launch: fork/join two-stream pipeline (graph-capturable) ========
extern "C" void kernel_launch(void* const* d_in, const int* in_sizes, int n_in,
                              void* d_out, int out_size)
{
    (void)in_sizes; (void)n_in; (void)out_size;
    const float* logits = (const float*)d_in[0];
    const float* gumb   = (const float*)d_in[1];
    const int*   inp    = (const int*)d_in[2];
    const int*   mask   = (const int*)d_in[3];
    const float* W      = (const float*)d_in[4];
    float* out = (float*)d_out;

    static cudaStream_t s2 = nullptr;
    static cudaEvent_t e0 = nullptr, es0 = nullptr, es1 = nullptr, eg = nullptr;
    if (!s2) {
        cudaStreamCreateWithFlags(&s2, cudaStreamNonBlocking);
        cudaEventCreateWithFlags(&e0,  cudaEventDisableTiming);
        cudaEventCreateWithFlags(&es0, cudaEventDisableTiming);
        cudaEventCreateWithFlags(&es1, cudaEventDisableTiming);
        cudaEventCreateWithFlags(&eg,  cudaEventDisableTiming);
    }

    // fork side stream from the launch stream
    cudaEventRecord(e0, 0);
    cudaStreamWaitEvent(s2, e0, 0);

    // side stream: W convert + row scan (independent of stats)
    k_wconv<<<VV / TK, 256, 0, s2>>>(W, mask);

    // main stream: stats in two halves
    dim3 gsH(PP, NSEG / 2);
    k_stats<<<gsH, NT1, 0, 0>>>(logits, gumb, mask, 0);
    cudaEventRecord(es0, 0);
    k_stats<<<gsH, NT1, 0, 0>>>(logits, gumb, mask, NSEG / 2);
    cudaEventRecord(es1, 0);
    k_comb<<<PP / 8, 256, 0, 0>>>(inp, mask, W, out);   // needs all stats

    // side stream: GEMM halves, each gated on its stats half
    dim3 ggH(PP / MT, GNSPLIT / 2);
    cudaStreamWaitEvent(s2, es0, 0);
    k_gemm<<<ggH, GTHR, 0, s2>>>(0);
    cudaStreamWaitEvent(s2, es1, 0);
    k_gemm<<<ggH, GTHR, 0, s2>>>(GNSPLIT / 2);
    cudaEventRecord(eg, s2);

    // join: reduce needs comb (main) + gemm (side)
    cudaStreamWaitEvent(0, eg, 0);
    k_red<<<PP, 256, 0, 0>>>(mask, out);
}